// round 3
// baseline (speedup 1.0000x reference)
#include <cuda_runtime.h>

#define T_LEN 512
#define B_SZ  512
#define I_SZ  100
#define H_SZ  96
#define G3    288   // 3*H
#define BCH   8     // batch rows per scan block

// Scratch: input projections for both directions: [2][T][B][3H] fp32 = 604MB
static __device__ float g_xproj[2ull * T_LEN * B_SZ * G3];

__device__ __forceinline__ float fast_sigmoid(float x) {
    // 1/(1+exp(-x)) via ex2.approx + rcp.approx  (error ~1e-6)
    float e, r;
    asm("ex2.approx.f32 %0, %1;" : "=f"(e) : "f"(-1.4426950408889634f * x));
    asm("rcp.approx.f32 %0, %1;" : "=f"(r) : "f"(1.0f + e));
    return r;
}
__device__ __forceinline__ float fast_tanh(float x) {
    // tanh(x) = 2/(1+exp(-2x)) - 1
    float e, r;
    asm("ex2.approx.f32 %0, %1;" : "=f"(e) : "f"(-2.8853900817779268f * x));
    asm("rcp.approx.f32 %0, %1;" : "=f"(r) : "f"(1.0f + e));
    return 2.0f * r - 1.0f;
}

// ---------------------------------------------------------------------------
// Projection: g_xproj[dir][row][g] = b_ih[g] + sum_k x[row][k] * w_ih[g][k]
// One thread per g (288 threads). W row (100 floats) lives in registers.
// x rows staged to smem (double-buffered), broadcast-read as float4.
// ---------------------------------------------------------------------------
__global__ __launch_bounds__(G3, 1) void proj_kernel(
    const float* __restrict__ x,
    const float* __restrict__ w_ih_f, const float* __restrict__ b_ih_f,
    const float* __restrict__ w_ih_b, const float* __restrict__ b_ih_b)
{
    const int dir    = blockIdx.x & 1;
    const int chunk  = blockIdx.x >> 1;
    const int nchunk = gridDim.x >> 1;
    const long R = (long)T_LEN * B_SZ;
    const long rows_per = (R + nchunk - 1) / nchunk;
    const long r0 = (long)chunk * rows_per;
    const long r1 = (r0 + rows_per < R) ? (r0 + rows_per) : R;

    const float* w    = dir ? w_ih_b : w_ih_f;
    const float* bias = dir ? b_ih_b : b_ih_f;
    float* xp = g_xproj + (size_t)dir * T_LEN * B_SZ * G3;

    const int g = threadIdx.x;
    float wr[I_SZ];
    #pragma unroll
    for (int k = 0; k < I_SZ; k++) wr[k] = w[g * I_SZ + k];
    const float bg = bias[g];

    // double-buffered stage: 16 rows x 100 floats = 400 float4 per buffer
    __shared__ __align__(16) float4 xs4[2][16 * 25];

    // prime buffer 0
    {
        long row0 = r0;
        int nr = (int)((r1 - row0 < 16) ? (r1 - row0) : 16);
        const float4* src = (const float4*)(x + row0 * I_SZ);
        for (int idx = g; idx < nr * 25; idx += G3) xs4[0][idx] = src[idx];
    }
    __syncthreads();

    int buf = 0;
    for (long row0 = r0; row0 < r1; row0 += 16, buf ^= 1) {
        const int nr = (int)((r1 - row0 < 16) ? (r1 - row0) : 16);

        // issue prefetch of next tile into registers (latency hidden by compute)
        float4 pre0, pre1;
        int pcount = 0;
        const long nrow0 = row0 + 16;
        if (nrow0 < r1) {
            const int nnr = (int)((r1 - nrow0 < 16) ? (r1 - nrow0) : 16);
            const float4* nsrc = (const float4*)(x + nrow0 * I_SZ);
            if (g < nnr * 25)        { pre0 = nsrc[g];       pcount = 1; }
            if (g + G3 < nnr * 25)   { pre1 = nsrc[g + G3];  pcount = 2; }
        }

        // compute tile: 4 rows at a time for ILP
        const float4* xb = xs4[buf];
        for (int sub = 0; sub < nr; sub += 4) {
            float acc0 = bg, acc1 = bg, acc2 = bg, acc3 = bg;
            #pragma unroll
            for (int k4 = 0; k4 < 25; k4++) {
                float4 a = xb[(sub + 0) * 25 + k4];
                float4 b = xb[(sub + 1) * 25 + k4];
                float4 c = xb[(sub + 2) * 25 + k4];
                float4 d = xb[(sub + 3) * 25 + k4];
                acc0 = fmaf(a.x, wr[4*k4+0], acc0);
                acc0 = fmaf(a.y, wr[4*k4+1], acc0);
                acc0 = fmaf(a.z, wr[4*k4+2], acc0);
                acc0 = fmaf(a.w, wr[4*k4+3], acc0);
                acc1 = fmaf(b.x, wr[4*k4+0], acc1);
                acc1 = fmaf(b.y, wr[4*k4+1], acc1);
                acc1 = fmaf(b.z, wr[4*k4+2], acc1);
                acc1 = fmaf(b.w, wr[4*k4+3], acc1);
                acc2 = fmaf(c.x, wr[4*k4+0], acc2);
                acc2 = fmaf(c.y, wr[4*k4+1], acc2);
                acc2 = fmaf(c.z, wr[4*k4+2], acc2);
                acc2 = fmaf(c.w, wr[4*k4+3], acc2);
                acc3 = fmaf(d.x, wr[4*k4+0], acc3);
                acc3 = fmaf(d.y, wr[4*k4+1], acc3);
                acc3 = fmaf(d.z, wr[4*k4+2], acc3);
                acc3 = fmaf(d.w, wr[4*k4+3], acc3);
            }
            if (row0 + sub + 0 < r1) xp[(row0 + sub + 0) * G3 + g] = acc0;
            if (row0 + sub + 1 < r1) xp[(row0 + sub + 1) * G3 + g] = acc1;
            if (row0 + sub + 2 < r1) xp[(row0 + sub + 2) * G3 + g] = acc2;
            if (row0 + sub + 3 < r1) xp[(row0 + sub + 3) * G3 + g] = acc3;
        }

        // store prefetched tile into alternate buffer
        if (pcount >= 1) xs4[buf ^ 1][g] = pre0;
        if (pcount >= 2) xs4[buf ^ 1][g + G3] = pre1;
        __syncthreads();
    }
}

// ---------------------------------------------------------------------------
// Scan: each block owns BCH batch rows for one direction, loops over all T.
// One thread per gate column g; W_hh row (96 floats) in registers.
// h kept in smem, broadcast-read as float4.
// ---------------------------------------------------------------------------
__global__ __launch_bounds__(G3, 1) void scan_kernel(
    const float* __restrict__ w_hh_f, const float* __restrict__ b_hh_f,
    const float* __restrict__ w_hh_b, const float* __restrict__ b_hh_b,
    float* __restrict__ out)
{
    const int dir = blockIdx.y;
    const int b0  = blockIdx.x * BCH;
    const float* w    = dir ? w_hh_b : w_hh_f;
    const float* bias = dir ? b_hh_b : b_hh_f;
    const float* xp = g_xproj + (size_t)dir * T_LEN * B_SZ * G3;

    const int g = threadIdx.x;
    float wr[H_SZ];
    #pragma unroll
    for (int k = 0; k < H_SZ; k++) wr[k] = w[g * H_SZ + k];
    const float bg = bias[g];

    __shared__ __align__(16) float h_s[BCH][H_SZ];   // hidden state
    __shared__ float s_s[BCH][G3];                   // r,z: xp+hp ; n: hp
    __shared__ float xn_s[BCH][H_SZ];                // xp for n-gate

    for (int idx = g; idx < BCH * H_SZ; idx += G3) ((float*)h_s)[idx] = 0.0f;
    __syncthreads();

    for (int it = 0; it < T_LEN; it++) {
        const int t = dir ? (T_LEN - 1 - it) : it;

        // load this step's x-projection early (latency overlapped with matmul)
        float xq[BCH];
        const float* xpt = xp + ((size_t)t * B_SZ + b0) * G3 + g;
        #pragma unroll
        for (int b = 0; b < BCH; b++) xq[b] = xpt[(size_t)b * G3];

        // hp[b][g] = bias[g] + dot(W_hh[g], h[b])
        float acc[BCH];
        #pragma unroll
        for (int b = 0; b < BCH; b++) acc[b] = bg;
        const float4* h4 = (const float4*)h_s;       // [BCH][24]
        #pragma unroll
        for (int k4 = 0; k4 < H_SZ / 4; k4++) {
            #pragma unroll
            for (int b = 0; b < BCH; b++) {
                float4 hv = h4[b * (H_SZ / 4) + k4];
                acc[b] = fmaf(hv.x, wr[4*k4+0], acc[b]);
                acc[b] = fmaf(hv.y, wr[4*k4+1], acc[b]);
                acc[b] = fmaf(hv.z, wr[4*k4+2], acc[b]);
                acc[b] = fmaf(hv.w, wr[4*k4+3], acc[b]);
            }
        }

        // stage pre-activations
        if (g < 2 * H_SZ) {
            #pragma unroll
            for (int b = 0; b < BCH; b++) s_s[b][g] = acc[b] + xq[b];
        } else {
            #pragma unroll
            for (int b = 0; b < BCH; b++) {
                s_s[b][g] = acc[b];               // hp_n (r multiplies this)
                xn_s[b][g - 2 * H_SZ] = xq[b];    // xp_n
            }
        }
        __syncthreads();

        // gates: 768 outputs (8 b x 96 j); thread handles o = g, g+288, g+576
        #pragma unroll
        for (int oo = 0; oo < 3; oo++) {
            const int o = g + oo * G3;
            if (o < BCH * H_SZ) {
                const int b = o / H_SZ;
                const int j = o % H_SZ;
                const float r = fast_sigmoid(s_s[b][j]);
                const float z = fast_sigmoid(s_s[b][H_SZ + j]);
                const float n = fast_tanh(fmaf(r, s_s[b][2 * H_SZ + j], xn_s[b][j]));
                const float hold = h_s[b][j];
                const float hn = fmaf(z, hold - n, n);   // (1-z)*n + z*h
                h_s[b][j] = hn;
                out[((size_t)t * B_SZ + (b0 + b)) * (2 * H_SZ) + dir * H_SZ + j] = hn;
            }
        }
        __syncthreads();
    }
}

extern "C" void kernel_launch(void* const* d_in, const int* in_sizes, int n_in,
                              void* d_out, int out_size) {
    const float* x    = (const float*)d_in[0];
    const float* wihf = (const float*)d_in[1];
    const float* whhf = (const float*)d_in[2];
    const float* bihf = (const float*)d_in[3];
    const float* bhhf = (const float*)d_in[4];
    const float* wihb = (const float*)d_in[5];
    const float* whhb = (const float*)d_in[6];
    const float* bihb = (const float*)d_in[7];
    const float* bhhb = (const float*)d_in[8];
    float* out = (float*)d_out;

    proj_kernel<<<148, G3>>>(x, wihf, bihf, wihb, bihb);
    dim3 sg(B_SZ / BCH, 2);
    scan_kernel<<<sg, G3>>>(whhf, bhhf, whhb, bhhb, out);
}

// round 5
// speedup vs baseline: 1.1316x; 1.1316x over previous
#include <cuda_runtime.h>

#define T_LEN 512
#define B_SZ  512
#define I_SZ  100
#define H_SZ  96
#define G3    288   // 3*H
#define BCH   7     // batch rows per scan block (74 chunks x 2 dirs = 148 blocks)
#define NCHUNK 74

typedef unsigned long long u64;

// Scratch: input projections for both directions: [2][T][B][3H] fp32
static __device__ float g_xproj[2ull * T_LEN * B_SZ * G3];

// ---- packed fp32x2 helpers (sm_103a FFMA2 path; bit-identical to 2x fmaf) ----
__device__ __forceinline__ u64 ffma2(u64 a, u64 b, u64 c) {
    u64 d;
    asm("fma.rn.f32x2 %0, %1, %2, %3;" : "=l"(d) : "l"(a), "l"(b), "l"(c));
    return d;
}
__device__ __forceinline__ u64 pack2(float lo, float hi) {
    u64 p;
    asm("mov.b64 %0, {%1, %2};" : "=l"(p) : "f"(lo), "f"(hi));
    return p;
}
__device__ __forceinline__ float hsum2(u64 p) {
    float lo, hi;
    asm("mov.b64 {%0, %1}, %2;" : "=f"(lo), "=f"(hi) : "l"(p));
    return lo + hi;
}

__device__ __forceinline__ float fast_sigmoid(float x) {
    float e, r;
    asm("ex2.approx.f32 %0, %1;" : "=f"(e) : "f"(-1.4426950408889634f * x));
    asm("rcp.approx.f32 %0, %1;" : "=f"(r) : "f"(1.0f + e));
    return r;
}
__device__ __forceinline__ float fast_tanh(float x) {
    float e, r;
    asm("ex2.approx.f32 %0, %1;" : "=f"(e) : "f"(-2.8853900817779268f * x));
    asm("rcp.approx.f32 %0, %1;" : "=f"(r) : "f"(1.0f + e));
    return 2.0f * r - 1.0f;
}

// ---------------------------------------------------------------------------
// Projection: g_xproj[dir][row][g] = b_ih[g] + sum_k x[row][k] * w_ih[g][k]
// One thread per g (288 threads). Weight row (50 packed f32x2) in registers.
// x rows staged to smem (double-buffered), broadcast-read as 16B pairs.
// ---------------------------------------------------------------------------
__global__ __launch_bounds__(G3, 1) void proj_kernel(
    const float* __restrict__ x,
    const float* __restrict__ w_ih_f, const float* __restrict__ b_ih_f,
    const float* __restrict__ w_ih_b, const float* __restrict__ b_ih_b)
{
    const int dir    = blockIdx.x & 1;
    const int chunk  = blockIdx.x >> 1;
    const int nchunk = gridDim.x >> 1;
    const long R = (long)T_LEN * B_SZ;
    const long rows_per = (R + nchunk - 1) / nchunk;
    const long r0 = (long)chunk * rows_per;
    const long r1 = (r0 + rows_per < R) ? (r0 + rows_per) : R;

    const float* w    = dir ? w_ih_b : w_ih_f;
    const float* bias = dir ? b_ih_b : b_ih_f;
    float* xp = g_xproj + (size_t)dir * T_LEN * B_SZ * G3;

    const int g = threadIdx.x;
    // weight row: 100 floats = 50 packed f32x2 (byte offset 400*g is 8-aligned)
    u64 wr2[I_SZ / 2];
    {
        const u64* wrow = (const u64*)(w + g * I_SZ);
        #pragma unroll
        for (int k = 0; k < I_SZ / 2; k++) wr2[k] = wrow[k];
    }
    const float bg = bias[g];

    // double-buffered stage: 16 rows x 100 floats = 400 float4 per buffer
    __shared__ __align__(16) float4 xs4[2][16 * 25];

    // prime buffer 0
    {
        long row0 = r0;
        int nr = (int)((r1 - row0 < 16) ? (r1 - row0) : 16);
        const float4* src = (const float4*)(x + row0 * I_SZ);
        for (int idx = g; idx < nr * 25; idx += G3) xs4[0][idx] = src[idx];
    }
    __syncthreads();

    int buf = 0;
    for (long row0 = r0; row0 < r1; row0 += 16, buf ^= 1) {
        const int nr = (int)((r1 - row0 < 16) ? (r1 - row0) : 16);

        // prefetch next tile into registers (latency hidden by compute)
        float4 pre0, pre1;
        int pcount = 0;
        const long nrow0 = row0 + 16;
        if (nrow0 < r1) {
            const int nnr = (int)((r1 - nrow0 < 16) ? (r1 - nrow0) : 16);
            const float4* nsrc = (const float4*)(x + nrow0 * I_SZ);
            if (g < nnr * 25)        { pre0 = nsrc[g];       pcount = 1; }
            if (g + G3 < nnr * 25)   { pre1 = nsrc[g + G3];  pcount = 2; }
        }

        const ulonglong2* xb2 = (const ulonglong2*)xs4[buf];  // [row][25] 16B pairs
        for (int sub = 0; sub < nr; sub += 4) {
            u64 a0 = pack2(bg, 0.0f);
            u64 a1 = pack2(bg, 0.0f);
            u64 a2 = pack2(bg, 0.0f);
            u64 a3 = pack2(bg, 0.0f);
            #pragma unroll
            for (int k4 = 0; k4 < 25; k4++) {
                ulonglong2 va = xb2[(sub + 0) * 25 + k4];
                ulonglong2 vb = xb2[(sub + 1) * 25 + k4];
                ulonglong2 vc = xb2[(sub + 2) * 25 + k4];
                ulonglong2 vd = xb2[(sub + 3) * 25 + k4];
                a0 = ffma2(va.x, wr2[2 * k4],     a0);
                a0 = ffma2(va.y, wr2[2 * k4 + 1], a0);
                a1 = ffma2(vb.x, wr2[2 * k4],     a1);
                a1 = ffma2(vb.y, wr2[2 * k4 + 1], a1);
                a2 = ffma2(vc.x, wr2[2 * k4],     a2);
                a2 = ffma2(vc.y, wr2[2 * k4 + 1], a2);
                a3 = ffma2(vd.x, wr2[2 * k4],     a3);
                a3 = ffma2(vd.y, wr2[2 * k4 + 1], a3);
            }
            if (row0 + sub + 0 < r1) xp[(row0 + sub + 0) * G3 + g] = hsum2(a0);
            if (row0 + sub + 1 < r1) xp[(row0 + sub + 1) * G3 + g] = hsum2(a1);
            if (row0 + sub + 2 < r1) xp[(row0 + sub + 2) * G3 + g] = hsum2(a2);
            if (row0 + sub + 3 < r1) xp[(row0 + sub + 3) * G3 + g] = hsum2(a3);
        }

        if (pcount >= 1) xs4[buf ^ 1][g] = pre0;
        if (pcount >= 2) xs4[buf ^ 1][g + G3] = pre1;
        __syncthreads();
    }
}

// ---------------------------------------------------------------------------
// Scan: each block owns BCH batch rows for one direction, loops over all T.
// One thread per gate column g; W_hh row (48 packed f32x2) in registers.
// h kept in smem, broadcast-read 16B at a time.
// ---------------------------------------------------------------------------
__global__ __launch_bounds__(G3, 1) void scan_kernel(
    const float* __restrict__ w_hh_f, const float* __restrict__ b_hh_f,
    const float* __restrict__ w_hh_b, const float* __restrict__ b_hh_b,
    float* __restrict__ out)
{
    const int dir = blockIdx.y;
    const int b0  = blockIdx.x * BCH;
    const float* w    = dir ? w_hh_b : w_hh_f;
    const float* bias = dir ? b_hh_b : b_hh_f;
    const float* xp = g_xproj + (size_t)dir * T_LEN * B_SZ * G3;

    const int g = threadIdx.x;
    // weight row: 96 floats = 48 packed f32x2 (byte offset 384*g is 8-aligned)
    u64 wr2[H_SZ / 2];
    {
        const u64* wrow = (const u64*)(w + g * H_SZ);
        #pragma unroll
        for (int k = 0; k < H_SZ / 2; k++) wr2[k] = wrow[k];
    }
    const float bg = bias[g];

    __shared__ __align__(16) float h_s[BCH][H_SZ];   // hidden state
    __shared__ float s_s[BCH][G3];                   // r,z: xp+hp ; n: hp
    __shared__ float xn_s[BCH][H_SZ];                // xp for n-gate

    for (int idx = g; idx < BCH * H_SZ; idx += G3) ((float*)h_s)[idx] = 0.0f;
    __syncthreads();

    for (int it = 0; it < T_LEN; it++) {
        const int t = dir ? (T_LEN - 1 - it) : it;

        // load this step's x-projection early (latency overlapped with matmul)
        float xq[BCH];
        #pragma unroll
        for (int b = 0; b < BCH; b++) {
            int row = b0 + b;
            if (row > B_SZ - 1) row = B_SZ - 1;   // tail-chunk clamp (no OOB)
            xq[b] = xp[((size_t)t * B_SZ + row) * G3 + g];
        }

        // hp[b][g] = bias[g] + dot(W_hh[g], h[b])  -- packed f32x2 FMAs
        u64 acc2[BCH];
        #pragma unroll
        for (int b = 0; b < BCH; b++) acc2[b] = pack2(bg, 0.0f);
        const ulonglong2* h2 = (const ulonglong2*)h_s;   // [BCH][24] 16B pairs
        #pragma unroll
        for (int k4 = 0; k4 < H_SZ / 4; k4++) {
            #pragma unroll
            for (int b = 0; b < BCH; b++) {
                ulonglong2 hv = h2[b * (H_SZ / 4) + k4];
                acc2[b] = ffma2(hv.x, wr2[2 * k4],     acc2[b]);
                acc2[b] = ffma2(hv.y, wr2[2 * k4 + 1], acc2[b]);
            }
        }

        // stage pre-activations
        if (g < 2 * H_SZ) {
            #pragma unroll
            for (int b = 0; b < BCH; b++) s_s[b][g] = hsum2(acc2[b]) + xq[b];
        } else {
            #pragma unroll
            for (int b = 0; b < BCH; b++) {
                s_s[b][g] = hsum2(acc2[b]);       // hp_n (r multiplies this)
                xn_s[b][g - 2 * H_SZ] = xq[b];    // xp_n
            }
        }
        __syncthreads();

        // gates: BCH*96 = 672 outputs; thread handles o = g, g+288, g+576
        #pragma unroll
        for (int oo = 0; oo < 3; oo++) {
            const int o = g + oo * G3;
            if (o < BCH * H_SZ) {
                const int b = o / H_SZ;
                const int j = o % H_SZ;
                const float r = fast_sigmoid(s_s[b][j]);
                const float z = fast_sigmoid(s_s[b][H_SZ + j]);
                const float n = fast_tanh(fmaf(r, s_s[b][2 * H_SZ + j], xn_s[b][j]));
                const float hold = h_s[b][j];
                const float hn = fmaf(z, hold - n, n);   // (1-z)*n + z*h
                h_s[b][j] = hn;
                if (b0 + b < B_SZ)
                    out[((size_t)t * B_SZ + (b0 + b)) * (2 * H_SZ) + dir * H_SZ + j] = hn;
            }
        }
        __syncthreads();
    }
}

extern "C" void kernel_launch(void* const* d_in, const int* in_sizes, int n_in,
                              void* d_out, int out_size) {
    const float* x    = (const float*)d_in[0];
    const float* wihf = (const float*)d_in[1];
    const float* whhf = (const float*)d_in[2];
    const float* bihf = (const float*)d_in[3];
    const float* bhhf = (const float*)d_in[4];
    const float* wihb = (const float*)d_in[5];
    const float* whhb = (const float*)d_in[6];
    const float* bihb = (const float*)d_in[7];
    const float* bhhb = (const float*)d_in[8];
    float* out = (float*)d_out;

    proj_kernel<<<148, G3>>>(x, wihf, bihf, wihb, bihb);
    dim3 sg(NCHUNK, 2);
    scan_kernel<<<sg, G3>>>(whhf, bhhf, whhb, bhhb, out);
}

// round 7
// speedup vs baseline: 1.1575x; 1.0229x over previous
#include <cuda_runtime.h>

#define T_LEN 512
#define B_SZ  512
#define I_SZ  100
#define H_SZ  96
#define G3    288   // 3*H
#define BCH   7     // batch rows per scan block (74 chunks x 2 dirs = 148 blocks)
#define NCHUNK 74
#define NTHR  576   // 2 threads per gate-row (split-k)

typedef unsigned long long u64;

// Scratch: input projections for both directions: [2][T][B][3H] fp32
static __device__ float g_xproj[2ull * T_LEN * B_SZ * G3];

// ---- packed fp32x2 helpers (sm_103a FFMA2 path; bit-identical to 2x fmaf) ----
__device__ __forceinline__ u64 ffma2(u64 a, u64 b, u64 c) {
    u64 d;
    asm("fma.rn.f32x2 %0, %1, %2, %3;" : "=l"(d) : "l"(a), "l"(b), "l"(c));
    return d;
}
__device__ __forceinline__ u64 pack2(float lo, float hi) {
    u64 p;
    asm("mov.b64 %0, {%1, %2};" : "=l"(p) : "f"(lo), "f"(hi));
    return p;
}
__device__ __forceinline__ float hsum2(u64 p) {
    float lo, hi;
    asm("mov.b64 {%0, %1}, %2;" : "=f"(lo), "=f"(hi) : "l"(p));
    return lo + hi;
}

__device__ __forceinline__ float fast_sigmoid(float x) {
    float e, r;
    asm("ex2.approx.f32 %0, %1;" : "=f"(e) : "f"(-1.4426950408889634f * x));
    asm("rcp.approx.f32 %0, %1;" : "=f"(r) : "f"(1.0f + e));
    return r;
}
__device__ __forceinline__ float fast_tanh(float x) {
    float e, r;
    asm("ex2.approx.f32 %0, %1;" : "=f"(e) : "f"(-2.8853900817779268f * x));
    asm("rcp.approx.f32 %0, %1;" : "=f"(r) : "f"(1.0f + e));
    return 2.0f * r - 1.0f;
}

// ---------------------------------------------------------------------------
// Projection: g_xproj[dir][row][g] = b_ih[g] + sum_k x[row][k] * w_ih[g][k]
// 576 threads: warp w covers g in [16w,16w+16); lanes 0-15 = k-half 0,
// lanes 16-31 = k-half 1. Halves combined with shfl.bfly(16).
// half0 owns k floats [0,48) (+2 zero-padded u64), half1 owns [48,100).
// ---------------------------------------------------------------------------
__global__ __launch_bounds__(NTHR, 1) void proj_kernel(
    const float* __restrict__ x,
    const float* __restrict__ w_ih_f, const float* __restrict__ b_ih_f,
    const float* __restrict__ w_ih_b, const float* __restrict__ b_ih_b)
{
    const int dir    = blockIdx.x & 1;
    const int chunk  = blockIdx.x >> 1;
    const int nchunk = gridDim.x >> 1;
    const long R = (long)T_LEN * B_SZ;
    const long rows_per = (R + nchunk - 1) / nchunk;
    const long r0 = (long)chunk * rows_per;
    const long r1 = (r0 + rows_per < R) ? (r0 + rows_per) : R;

    const float* w    = dir ? w_ih_b : w_ih_f;
    const float* bias = dir ? b_ih_b : b_ih_f;
    float* xp = g_xproj + (size_t)dir * T_LEN * B_SZ * G3;

    const int t    = threadIdx.x;
    const int lane = t & 31;
    const int g    = (t >> 5) * 16 + (lane & 15);
    const int half = (lane >> 4);           // 0 or 1

    // weight half-row: 26 u64. half0: floats [0,48) + 2 zero u64 (uniform loop).
    // half1: floats [48,100) = 26 u64. Byte offset g*400 + half*192: 8-aligned.
    u64 wr2[26];
    {
        const u64* wrow = (const u64*)(w + g * I_SZ + half * 48);
        #pragma unroll
        for (int k = 0; k < 24; k++) wr2[k] = wrow[k];
        wr2[24] = half ? wrow[24] : 0ull;
        wr2[25] = half ? wrow[25] : 0ull;
    }
    const float bg = half ? 0.0f : bias[g];   // bias counted once per pair

    // double-buffered stage: 16 rows x 100 floats = 400 float4 per buffer
    __shared__ __align__(16) float4 xs4[2][16 * 25];

    // prime buffer 0 (576 threads >= 400 slots: single pass)
    {
        int nr = (int)((r1 - r0 < 16) ? (r1 - r0) : 16);
        const float4* src = (const float4*)(x + r0 * I_SZ);
        if (t < nr * 25) xs4[0][t] = src[t];
    }
    __syncthreads();

    int buf = 0;
    for (long row0 = r0; row0 < r1; row0 += 16, buf ^= 1) {
        const int nr = (int)((r1 - row0 < 16) ? (r1 - row0) : 16);

        // prefetch next tile into a register (latency hidden by compute)
        float4 pre0;
        int pdo = 0;
        const long nrow0 = row0 + 16;
        if (nrow0 < r1) {
            const int nnr = (int)((r1 - nrow0 < 16) ? (r1 - nrow0) : 16);
            const float4* nsrc = (const float4*)(x + nrow0 * I_SZ);
            if (t < nnr * 25) { pre0 = nsrc[t]; pdo = 1; }
        }

        // this half's view of each staged row: pairs [half*12, half*12+13)
        const ulonglong2* xb2 = (const ulonglong2*)xs4[buf] + half * 12;
        for (int sub = 0; sub < nr; sub += 4) {
            u64 a0 = pack2(bg, 0.0f);
            u64 a1 = pack2(bg, 0.0f);
            u64 a2 = pack2(bg, 0.0f);
            u64 a3 = pack2(bg, 0.0f);
            #pragma unroll
            for (int kk = 0; kk < 13; kk++) {
                ulonglong2 va = xb2[(sub + 0) * 25 + kk];
                ulonglong2 vb = xb2[(sub + 1) * 25 + kk];
                ulonglong2 vc = xb2[(sub + 2) * 25 + kk];
                ulonglong2 vd = xb2[(sub + 3) * 25 + kk];
                a0 = ffma2(va.x, wr2[2 * kk],     a0);
                a0 = ffma2(va.y, wr2[2 * kk + 1], a0);
                a1 = ffma2(vb.x, wr2[2 * kk],     a1);
                a1 = ffma2(vb.y, wr2[2 * kk + 1], a1);
                a2 = ffma2(vc.x, wr2[2 * kk],     a2);
                a2 = ffma2(vc.y, wr2[2 * kk + 1], a2);
                a3 = ffma2(vd.x, wr2[2 * kk],     a3);
                a3 = ffma2(vd.y, wr2[2 * kk + 1], a3);
            }
            // combine k-halves: after bfly both halves hold the full sums
            float s0 = hsum2(a0); s0 += __shfl_xor_sync(0xffffffffu, s0, 16);
            float s1 = hsum2(a1); s1 += __shfl_xor_sync(0xffffffffu, s1, 16);
            float s2 = hsum2(a2); s2 += __shfl_xor_sync(0xffffffffu, s2, 16);
            float s3 = hsum2(a3); s3 += __shfl_xor_sync(0xffffffffu, s3, 16);
            // split the 4 row-stores between the halves
            if (half == 0) {
                if (row0 + sub + 0 < r1) xp[(row0 + sub + 0) * G3 + g] = s0;
                if (row0 + sub + 1 < r1) xp[(row0 + sub + 1) * G3 + g] = s1;
            } else {
                if (row0 + sub + 2 < r1) xp[(row0 + sub + 2) * G3 + g] = s2;
                if (row0 + sub + 3 < r1) xp[(row0 + sub + 3) * G3 + g] = s3;
            }
        }

        if (pdo) xs4[buf ^ 1][t] = pre0;
        __syncthreads();
    }
}

// ---------------------------------------------------------------------------
// Scan: block owns BCH batch rows for one direction, loops over all T.
// 576 threads: 2 k-halves per gate-row g (lanes l / l^16), shfl-combined.
// h in smem (broadcast 16B reads); xq software-pipelined one step ahead.
// ---------------------------------------------------------------------------
__global__ __launch_bounds__(NTHR, 1) void scan_kernel(
    const float* __restrict__ w_hh_f, const float* __restrict__ b_hh_f,
    const float* __restrict__ w_hh_b, const float* __restrict__ b_hh_b,
    float* __restrict__ out)
{
    const int dir = blockIdx.y;
    const int b0  = blockIdx.x * BCH;
    const float* w    = dir ? w_hh_b : w_hh_f;
    const float* bias = dir ? b_hh_b : b_hh_f;
    const float* xp = g_xproj + (size_t)dir * T_LEN * B_SZ * G3;

    const int t    = threadIdx.x;
    const int lane = t & 31;
    const int g    = (t >> 5) * 16 + (lane & 15);
    const int half = (lane >> 4);

    // weight half-row: 48 floats = 24 u64 (byte offset g*384 + half*192: 8-aligned)
    u64 wr2[24];
    {
        const u64* wrow = (const u64*)(w + g * H_SZ + half * 48);
        #pragma unroll
        for (int k = 0; k < 24; k++) wr2[k] = wrow[k];
    }
    const float bg = half ? 0.0f : bias[g];

    __shared__ __align__(16) float h_s[BCH][H_SZ];   // hidden state
    __shared__ float s_s[BCH][G3];                   // r,z: xp+hp ; n: hp
    __shared__ float xn_s[BCH][H_SZ];                // xp for n-gate

    for (int idx = t; idx < BCH * H_SZ; idx += NTHR) ((float*)h_s)[idx] = 0.0f;
    __syncthreads();

    // clamped batch rows for this chunk (tail chunk safety)
    int brow[BCH];
    #pragma unroll
    for (int b = 0; b < BCH; b++) {
        int r = b0 + b;
        brow[b] = (r > B_SZ - 1) ? (B_SZ - 1) : r;
    }

    // prime xq pipeline for step 0 (only half0 stages, so only half0 loads)
    float xq[BCH];
    {
        const int t0 = dir ? (T_LEN - 1) : 0;
        if (half == 0) {
            #pragma unroll
            for (int b = 0; b < BCH; b++)
                xq[b] = xp[((size_t)t0 * B_SZ + brow[b]) * G3 + g];
        }
    }

    for (int it = 0; it < T_LEN; it++) {
        const int tc = dir ? (T_LEN - 1 - it) : it;

        // issue next step's xq loads now; consumed ~2 phases later (DRAM hidden)
        float xq_n[BCH];
        if (it + 1 < T_LEN && half == 0) {
            const int tn = dir ? (T_LEN - 2 - it) : (it + 1);
            #pragma unroll
            for (int b = 0; b < BCH; b++)
                xq_n[b] = xp[((size_t)tn * B_SZ + brow[b]) * G3 + g];
        }

        // hp[b][g] = bias[g] + dot(W_hh[g], h[b])  -- split-k packed FMAs
        u64 acc2[BCH];
        #pragma unroll
        for (int b = 0; b < BCH; b++) acc2[b] = pack2(bg, 0.0f);
        // per b: 24 ulonglong2 (96 floats); this half reads pairs [half*12, +12)
        const ulonglong2* h2 = (const ulonglong2*)h_s + half * 12;
        #pragma unroll
        for (int kk = 0; kk < 12; kk++) {
            #pragma unroll
            for (int b = 0; b < BCH; b++) {
                ulonglong2 hv = h2[b * 24 + kk];
                acc2[b] = ffma2(hv.x, wr2[2 * kk],     acc2[b]);
                acc2[b] = ffma2(hv.y, wr2[2 * kk + 1], acc2[b]);
            }
        }

        // combine halves + stage pre-activations (half0 writes)
        #pragma unroll
        for (int b = 0; b < BCH; b++) {
            float v = hsum2(acc2[b]);
            v += __shfl_xor_sync(0xffffffffu, v, 16);
            if (half == 0) {
                if (g < 2 * H_SZ) {
                    s_s[b][g] = v + xq[b];
                } else {
                    s_s[b][g] = v;                 // hp_n (r multiplies this)
                    xn_s[b][g - 2 * H_SZ] = xq[b]; // xp_n
                }
            }
            xq[b] = xq_n[b];
        }
        __syncthreads();

        // gates: BCH*96 = 672 outputs over 576 threads (2nd pass for t < 96)
        #pragma unroll
        for (int oo = 0; oo < 2; oo++) {
            const int o = t + oo * NTHR;
            if (o < BCH * H_SZ) {
                const int b = o / H_SZ;
                const int j = o % H_SZ;
                const float r = fast_sigmoid(s_s[b][j]);
                const float z = fast_sigmoid(s_s[b][H_SZ + j]);
                const float n = fast_tanh(fmaf(r, s_s[b][2 * H_SZ + j], xn_s[b][j]));
                const float hold = h_s[b][j];
                const float hn = fmaf(z, hold - n, n);   // (1-z)*n + z*h
                h_s[b][j] = hn;
                if (b0 + b < B_SZ)
                    out[((size_t)tc * B_SZ + (b0 + b)) * (2 * H_SZ) + dir * H_SZ + j] = hn;
            }
        }
        __syncthreads();
    }
}

extern "C" void kernel_launch(void* const* d_in, const int* in_sizes, int n_in,
                              void* d_out, int out_size) {
    const float* x    = (const float*)d_in[0];
    const float* wihf = (const float*)d_in[1];
    const float* whhf = (const float*)d_in[2];
    const float* bihf = (const float*)d_in[3];
    const float* bhhf = (const float*)d_in[4];
    const float* wihb = (const float*)d_in[5];
    const float* whhb = (const float*)d_in[6];
    const float* bihb = (const float*)d_in[7];
    const float* bhhb = (const float*)d_in[8];
    float* out = (float*)d_out;

    proj_kernel<<<148, NTHR>>>(x, wihf, bihf, wihb, bihb);
    dim3 sg(NCHUNK, 2);
    scan_kernel<<<sg, NTHR>>>(whhf, bhhf, whhb, bhhb, out);
}